// round 14
// baseline (speedup 1.0000x reference)
#include <cuda_runtime.h>
#include <cuda_fp16.h>
#include <math.h>
#include <stdint.h>

#define D_MODEL 2048
#define N_HEADS 16
#define D_HEAD  128
#define B_      4
#define T_      2048
#define M_TOTAL (B_*T_)   // 8192
#define NW      (D_MODEL*D_MODEL)   // 4194304 = 2^22

// Scratch: __device__ globals (no allocation allowed in kernel_launch).
__device__ __half g_qh[M_TOTAL*D_MODEL];     // fp16 q (rope'd)
__device__ __half g_kh[M_TOTAL*D_MODEL];     // fp16 k (rope'd)
__device__ __half g_vt[M_TOTAL*D_MODEL];     // fp16 v, transposed [b,h][d][t]
__device__ __half g_xh[M_TOTAL*D_MODEL];     // fp16 activations (x, then attn-out)
__device__ __half g_wh[4*NW];                // fp16 weights [wq|wk|wv|wo]

__device__ __forceinline__ uint32_t packh2(float a, float b) {
    __half2 h = __floats2half2_rn(a, b);
    return *(uint32_t*)&h;
}

// One fused fp32->fp16 conversion: x (regions 0..3 of NW) then wq/wk/wv/wo.
__global__ void conv_all(const float* __restrict__ x,
                         const float* __restrict__ wq, const float* __restrict__ wk,
                         const float* __restrict__ wv, const float* __restrict__ wo,
                         __half* __restrict__ xh, __half* __restrict__ wh) {
    size_t i = ((size_t)blockIdx.x * blockDim.x + threadIdx.x) * 4;
    int which = (int)(i >> 22);
    const float* src;
    __half* dst;
    if (which < 4) {
        src = x + i;
        dst = xh + i;
    } else {
        const float* w = (which == 4) ? wq : (which == 5) ? wk : (which == 6) ? wv : wo;
        src = w + (i & (NW - 1));
        dst = wh + (i - 4 * (size_t)NW);
    }
    float4 v = *(const float4*)src;
    uint2 pk;
    pk.x = packh2(v.x, v.y);
    pk.y = packh2(v.z, v.w);
    *(uint2*)dst = pk;
}

#define CP_ASYNC16(dst, src) \
    asm volatile("cp.async.cg.shared.global [%0], [%1], 16;" :: "r"(dst), "l"(src) : "memory")

__device__ __forceinline__ void mma_f16(float* d, const uint32_t* a, const uint32_t* b) {
    asm volatile(
        "mma.sync.aligned.m16n8k16.row.col.f32.f16.f16.f32 "
        "{%0,%1,%2,%3}, {%4,%5,%6,%7}, {%8,%9}, {%0,%1,%2,%3};"
        : "+f"(d[0]), "+f"(d[1]), "+f"(d[2]), "+f"(d[3])
        : "r"(a[0]), "r"(a[1]), "r"(a[2]), "r"(a[3]), "r"(b[0]), "r"(b[1]));
}

// ---------------------------------------------------------------------------
// GEMM (fp16 HMMA): Y = X @ W^T.  CTA 128x128, 4 warps (64x64), 3-stage.
// EPI=1: QKV — write fp16 q/k rows, v transposed [b,h][d][t].
// EPI=0: write fp32 to Yf.
// ---------------------------------------------------------------------------
#define CHH    64
#define SROWH  72
#define NSTH   3
#define STAGE_HALVES (256 * SROWH)
#define STAGE_B      (STAGE_HALVES * 2)
#define BOFF_B       (128 * SROWH * 2)
#define GEMM_SMEM    (NSTH * STAGE_B)       // 110592
#define NCHH  (D_MODEL / CHH)               // 32

template<int EPI>
__global__ __launch_bounds__(128, 2) void gemm5(const __half* __restrict__ X,
                                                const __half* __restrict__ W,
                                                __half* __restrict__ Yq,
                                                __half* __restrict__ Yk,
                                                __half* __restrict__ Yvt,
                                                float* __restrict__ Yf) {
    extern __shared__ __half smh[];
    const uint32_t smem_base = (uint32_t)__cvta_generic_to_shared(smh);

    const int tid  = threadIdx.x;
    const int wid  = tid >> 5;
    const int lane = tid & 31;
    const int qr   = lane >> 2;
    const int qc   = lane & 3;
    const int warpM = wid & 1;
    const int warpN = wid >> 1;

    const int m0      = blockIdx.y * 128;
    const int n_glob  = blockIdx.x * 128;
    const int which   = n_glob >> 11;
    const int n0      = n_glob & 2047;

    const __half* Arow = X + (size_t)m0 * D_MODEL;
    const __half* Brow = W + (size_t)n_glob * D_MODEL;

    float acc[4][8][4];
    #pragma unroll
    for (int mt = 0; mt < 4; mt++)
        #pragma unroll
        for (int nt = 0; nt < 8; nt++)
            #pragma unroll
            for (int c = 0; c < 4; c++) acc[mt][nt][c] = 0.f;

    auto prefetch = [&](int chunk, int stage) {
        const int k0 = chunk * CHH;
        const uint32_t sbase = smem_base + stage * STAGE_B;
        #pragma unroll
        for (int u = 0; u < 16; u++) {
            int idx = tid + u * 128;
            int isB = idx >> 10;
            int i2  = idx & 1023;
            int row = i2 >> 3;
            int seg = i2 & 7;
            const __half* src = (isB ? Brow : Arow) + (size_t)row * D_MODEL + k0 + seg * 8;
            uint32_t dst = sbase + (isB ? BOFF_B : 0) + row * (SROWH * 2) + seg * 16;
            CP_ASYNC16(dst, src);
        }
    };

    prefetch(0, 0);
    asm volatile("cp.async.commit_group;" ::: "memory");
    prefetch(1, 1);
    asm volatile("cp.async.commit_group;" ::: "memory");

    for (int i = 0; i < NCHH; i++) {
        const int stage = i % NSTH;
        asm volatile("cp.async.wait_group 1;" ::: "memory");
        __syncthreads();

        if (i + 2 < NCHH) prefetch(i + 2, (i + 2) % NSTH);
        asm volatile("cp.async.commit_group;" ::: "memory");

        const __half* Acur = smh + stage * STAGE_HALVES;
        const __half* Bcur = Acur + 128 * SROWH;

        #pragma unroll
        for (int k16 = 0; k16 < CHH; k16 += 16) {
            uint32_t a[4][4], b[8][2];
            #pragma unroll
            for (int mt = 0; mt < 4; mt++) {
                int r = warpM * 64 + mt * 16 + qr;
                a[mt][0] = *(const uint32_t*)&Acur[r * SROWH + k16 + 2 * qc];
                a[mt][1] = *(const uint32_t*)&Acur[(r + 8) * SROWH + k16 + 2 * qc];
                a[mt][2] = *(const uint32_t*)&Acur[r * SROWH + k16 + 8 + 2 * qc];
                a[mt][3] = *(const uint32_t*)&Acur[(r + 8) * SROWH + k16 + 8 + 2 * qc];
            }
            #pragma unroll
            for (int nt = 0; nt < 8; nt++) {
                int n = warpN * 64 + nt * 8 + qr;
                b[nt][0] = *(const uint32_t*)&Bcur[n * SROWH + k16 + 2 * qc];
                b[nt][1] = *(const uint32_t*)&Bcur[n * SROWH + k16 + 8 + 2 * qc];
            }
            #pragma unroll
            for (int mt = 0; mt < 4; mt++)
                #pragma unroll
                for (int nt = 0; nt < 8; nt++)
                    mma_f16(acc[mt][nt], a[mt], b[nt]);
        }
    }

    #pragma unroll
    for (int mt = 0; mt < 4; mt++) {
        #pragma unroll
        for (int nt = 0; nt < 8; nt++) {
            int r0 = m0 + warpM * 64 + mt * 16 + qr;
            int cc = n0 + warpN * 64 + nt * 8 + qc * 2;
            float o0 = acc[mt][nt][0], o1 = acc[mt][nt][1];
            float o2 = acc[mt][nt][2], o3 = acc[mt][nt][3];
            if (EPI == 0) {
                *(float2*)&Yf[(size_t)r0 * D_MODEL + cc]       = make_float2(o0, o1);
                *(float2*)&Yf[(size_t)(r0 + 8) * D_MODEL + cc] = make_float2(o2, o3);
            } else if (which < 2) {
                __half* Yh = (which == 0) ? Yq : Yk;
                *(uint32_t*)&Yh[(size_t)r0 * D_MODEL + cc]       = packh2(o0, o1);
                *(uint32_t*)&Yh[(size_t)(r0 + 8) * D_MODEL + cc] = packh2(o2, o3);
            } else {
                int hh = cc >> 7, d = cc & 127;
                int bb = r0 >> 11, tt = r0 & 2047;
                size_t base = ((size_t)(bb * N_HEADS + hh) * D_HEAD + d) * T_ + tt;
                Yvt[base]          = __float2half_rn(o0);
                Yvt[base + T_]     = __float2half_rn(o1);
                Yvt[base + 8]      = __float2half_rn(o2);
                Yvt[base + T_ + 8] = __float2half_rn(o3);
            }
        }
    }
}

// ---------------------------------------------------------------------------
// Vectorized RoPE in-place on fp16 q,k.
// ---------------------------------------------------------------------------
__global__ void rope_v(__half* __restrict__ q, __half* __restrict__ k,
                       const float* __restrict__ cosb, const float* __restrict__ sinb) {
    int idx = blockIdx.x * blockDim.x + threadIdx.x;   // B*T*H*8
    int seg = idx & 7;
    int h   = (idx >> 3) & (N_HEADS - 1);
    int t   = (idx >> 7) & (T_ - 1);
    int b   = idx >> 18;
    int d0  = seg * 8;
    size_t base = ((size_t)(b * T_ + t) * D_MODEL) + h * D_HEAD;

    float c0[8], s0[8], c1[8], s1[8];
    #pragma unroll
    for (int j = 0; j < 8; j += 4) {
        *(float4*)&c0[j] = *(const float4*)&cosb[t * D_HEAD + d0 + j];
        *(float4*)&s0[j] = *(const float4*)&sinb[t * D_HEAD + d0 + j];
        *(float4*)&c1[j] = *(const float4*)&cosb[t * D_HEAD + d0 + 64 + j];
        *(float4*)&s1[j] = *(const float4*)&sinb[t * D_HEAD + d0 + 64 + j];
    }

    union U8 { uint4 u; __half h[8]; };
    U8 qlo, qhi, klo, khi, oql, oqh, okl, okh;
    qlo.u = *(uint4*)&q[base + d0];
    qhi.u = *(uint4*)&q[base + d0 + 64];
    klo.u = *(uint4*)&k[base + d0];
    khi.u = *(uint4*)&k[base + d0 + 64];

    #pragma unroll
    for (int j = 0; j < 8; j++) {
        float ql = __half2float(qlo.h[j]), qh = __half2float(qhi.h[j]);
        oql.h[j] = __float2half_rn(ql * c0[j] - qh * s0[j]);
        oqh.h[j] = __float2half_rn(qh * c1[j] + ql * s1[j]);
        float kl = __half2float(klo.h[j]), kh = __half2float(khi.h[j]);
        okl.h[j] = __float2half_rn(kl * c0[j] - kh * s0[j]);
        okh.h[j] = __float2half_rn(kh * c1[j] + kl * s1[j]);
    }
    *(uint4*)&q[base + d0]      = oql.u;
    *(uint4*)&q[base + d0 + 64] = oqh.u;
    *(uint4*)&k[base + d0]      = okl.u;
    *(uint4*)&k[base + d0 + 64] = okh.u;
}

// ---------------------------------------------------------------------------
// fp16 flash attention (causal, m16n8k16).  EXACT R11 compute structure
// (no diagonal skips).  ONLY change: K/V tile loads via cp.async with
// 2-stage double buffering — tile kt+1 streams in under compute of kt.
// ---------------------------------------------------------------------------
#define BQ    64
#define BK    64
#define KPADH 136    // halves per Ks row (128 + 8)
#define VPADH 72     // halves per Vst row (64 + 8)
#define KS_HALVES   (BK * KPADH)                 // 8704
#define VS_HALVES   (D_HEAD * VPADH)             // 9216
#define ATTN_STAGEH (KS_HALVES + VS_HALVES)      // 17920 halves
#define ATTN_SMEM2  (2 * ATTN_STAGEH * 2)        // 71680 bytes

__global__ __launch_bounds__(128) void attn_f16(const __half* __restrict__ Q,
                                                const __half* __restrict__ K,
                                                const __half* __restrict__ vT,
                                                __half* __restrict__ O) {
    extern __shared__ __half smha[];
    const uint32_t smem_base = (uint32_t)__cvta_generic_to_shared(smha);

    const int qt = blockIdx.x, h = blockIdx.y, b = blockIdx.z;
    const int tid  = threadIdx.x;
    const int w    = tid >> 5;
    const int lane = tid & 31;
    const int qr   = lane >> 2;
    const int qc   = lane & 3;

    const int rowL0 = w * 16 + qr;
    const int rowL1 = rowL0 + 8;
    const size_t qg0 = (size_t)(b * T_ + qt * BQ + rowL0) * D_MODEL + h * D_HEAD;
    const size_t qg1 = qg0 + 8 * (size_t)D_MODEL;

    uint32_t qf[8][4];
    #pragma unroll
    for (int j = 0; j < 8; j++) {
        qf[j][0] = *(const uint32_t*)&Q[qg0 + j * 16 + 2 * qc];
        qf[j][1] = *(const uint32_t*)&Q[qg1 + j * 16 + 2 * qc];
        qf[j][2] = *(const uint32_t*)&Q[qg0 + j * 16 + 8 + 2 * qc];
        qf[j][3] = *(const uint32_t*)&Q[qg1 + j * 16 + 8 + 2 * qc];
    }

    float out[16][4];
    #pragma unroll
    for (int nt = 0; nt < 16; nt++)
        #pragma unroll
        for (int c = 0; c < 4; c++) out[nt][c] = 0.f;

    float m0 = -INFINITY, m1 = -INFINITY, l0 = 0.f, l1 = 0.f;
    const float scale = 0.08838834764831845f;

    const __half* kbase = K + (size_t)b * T_ * D_MODEL + h * D_HEAD;
    const __half* vbase = vT + (size_t)(b * N_HEADS + h) * D_HEAD * T_;

    // cp.async prefetch of tile kt into stage s
    auto prefetch_tile = [&](int kt, int s) {
        const uint32_t ks = smem_base + (uint32_t)(s * ATTN_STAGEH) * 2;
        const uint32_t vs = ks + KS_HALVES * 2;
        #pragma unroll
        for (int u = 0; u < 8; u++) {           // K tile: 1024 x 16B
            int it = tid + u * 128;
            int r = it >> 4, seg = it & 15;
            const __half* src = kbase + (size_t)(kt * BK + r) * D_MODEL + seg * 8;
            CP_ASYNC16(ks + (r * KPADH + seg * 8) * 2, src);
        }
        #pragma unroll
        for (int u = 0; u < 8; u++) {           // V^T tile: 1024 x 16B
            int it = tid + u * 128;
            int d = it >> 3, seg = it & 7;
            const __half* src = vbase + (size_t)d * T_ + kt * BK + seg * 8;
            CP_ASYNC16(vs + (d * VPADH + seg * 8) * 2, src);
        }
    };

    prefetch_tile(0, 0);
    asm volatile("cp.async.commit_group;" ::: "memory");

    for (int kt = 0; kt <= qt; kt++) {
        asm volatile("cp.async.wait_group 0;" ::: "memory");
        __syncthreads();   // tile kt resident; all warps done with the other stage

        if (kt < qt) {
            prefetch_tile(kt + 1, (kt + 1) & 1);
            asm volatile("cp.async.commit_group;" ::: "memory");
        }

        const __half* Ks  = smha + (kt & 1) * ATTN_STAGEH;
        const __half* Vst = Ks + KS_HALVES;

        float s[8][4];
        #pragma unroll
        for (int nt = 0; nt < 8; nt++)
            #pragma unroll
            for (int c = 0; c < 4; c++) s[nt][c] = 0.f;

        #pragma unroll
        for (int j = 0; j < 8; j++) {
            #pragma unroll
            for (int nt = 0; nt < 8; nt++) {
                uint32_t bf[2];
                bf[0] = *(const uint32_t*)&Ks[(nt * 8 + qr) * KPADH + j * 16 + 2 * qc];
                bf[1] = *(const uint32_t*)&Ks[(nt * 8 + qr) * KPADH + j * 16 + 8 + 2 * qc];
                mma_f16(s[nt], qf[j], bf);
            }
        }

        const bool diag = (kt == qt);
        #pragma unroll
        for (int nt = 0; nt < 8; nt++) {
            int c0 = nt * 8 + 2 * qc, c1 = c0 + 1;
            if (diag) {
                s[nt][0] = (c0 > rowL0) ? -INFINITY : s[nt][0] * scale;
                s[nt][1] = (c1 > rowL0) ? -INFINITY : s[nt][1] * scale;
                s[nt][2] = (c0 > rowL1) ? -INFINITY : s[nt][2] * scale;
                s[nt][3] = (c1 > rowL1) ? -INFINITY : s[nt][3] * scale;
            } else {
                s[nt][0] *= scale; s[nt][1] *= scale;
                s[nt][2] *= scale; s[nt][3] *= scale;
            }
        }

        float rmax0 = -INFINITY, rmax1 = -INFINITY;
        #pragma unroll
        for (int nt = 0; nt < 8; nt++) {
            rmax0 = fmaxf(rmax0, fmaxf(s[nt][0], s[nt][1]));
            rmax1 = fmaxf(rmax1, fmaxf(s[nt][2], s[nt][3]));
        }
        rmax0 = fmaxf(rmax0, __shfl_xor_sync(0xffffffffu, rmax0, 1));
        rmax0 = fmaxf(rmax0, __shfl_xor_sync(0xffffffffu, rmax0, 2));
        rmax1 = fmaxf(rmax1, __shfl_xor_sync(0xffffffffu, rmax1, 1));
        rmax1 = fmaxf(rmax1, __shfl_xor_sync(0xffffffffu, rmax1, 2));

        float mn0 = fmaxf(m0, rmax0), mn1 = fmaxf(m1, rmax1);
        float a0 = __expf(m0 - mn0),  a1 = __expf(m1 - mn1);

        uint32_t pr0[8], pr1[8];
        float sum0 = 0.f, sum1 = 0.f;
        #pragma unroll
        for (int nt = 0; nt < 8; nt++) {
            float p0 = __expf(s[nt][0] - mn0);
            float p1 = __expf(s[nt][1] - mn0);
            float p2 = __expf(s[nt][2] - mn1);
            float p3 = __expf(s[nt][3] - mn1);
            sum0 += p0 + p1; sum1 += p2 + p3;
            pr0[nt] = packh2(p0, p1);
            pr1[nt] = packh2(p2, p3);
        }
        sum0 += __shfl_xor_sync(0xffffffffu, sum0, 1);
        sum0 += __shfl_xor_sync(0xffffffffu, sum0, 2);
        sum1 += __shfl_xor_sync(0xffffffffu, sum1, 1);
        sum1 += __shfl_xor_sync(0xffffffffu, sum1, 2);

        l0 = l0 * a0 + sum0;
        l1 = l1 * a1 + sum1;
        m0 = mn0; m1 = mn1;

        #pragma unroll
        for (int nt = 0; nt < 16; nt++) {
            out[nt][0] *= a0; out[nt][1] *= a0;
            out[nt][2] *= a1; out[nt][3] *= a1;
        }

        #pragma unroll
        for (int j = 0; j < 4; j++) {
            uint32_t af[4] = { pr0[2 * j], pr1[2 * j], pr0[2 * j + 1], pr1[2 * j + 1] };
            #pragma unroll
            for (int nt = 0; nt < 16; nt++) {
                uint32_t bf[2];
                bf[0] = *(const uint32_t*)&Vst[(nt * 8 + qr) * VPADH + j * 16 + 2 * qc];
                bf[1] = *(const uint32_t*)&Vst[(nt * 8 + qr) * VPADH + j * 16 + 8 + 2 * qc];
                mma_f16(out[nt], af, bf);
            }
        }
    }

    float inv0 = 1.f / l0, inv1 = 1.f / l1;
    #pragma unroll
    for (int nt = 0; nt < 16; nt++) {
        int cc = nt * 8 + 2 * qc;
        *(uint32_t*)&O[qg0 + cc] = packh2(out[nt][0] * inv0, out[nt][1] * inv0);
        *(uint32_t*)&O[qg1 + cc] = packh2(out[nt][2] * inv1, out[nt][3] * inv1);
    }
}

// ---------------------------------------------------------------------------
extern "C" void kernel_launch(void* const* d_in, const int* in_sizes, int n_in,
                              void* d_out, int out_size) {
    const float* x  = (const float*)d_in[0];
    const float* rc = (const float*)d_in[1];
    const float* rs = (const float*)d_in[2];
    const float* wq = (const float*)d_in[3];
    const float* wk = (const float*)d_in[4];
    const float* wv = (const float*)d_in[5];
    const float* wo = (const float*)d_in[6];
    float* out = (float*)d_out;

    __half *qh, *kh, *vt, *xh, *wh;
    cudaGetSymbolAddress((void**)&qh, g_qh);
    cudaGetSymbolAddress((void**)&kh, g_kh);
    cudaGetSymbolAddress((void**)&vt, g_vt);
    cudaGetSymbolAddress((void**)&xh, g_xh);
    cudaGetSymbolAddress((void**)&wh, g_wh);

    cudaFuncSetAttribute(gemm5<1>, cudaFuncAttributeMaxDynamicSharedMemorySize, GEMM_SMEM);
    cudaFuncSetAttribute(gemm5<0>, cudaFuncAttributeMaxDynamicSharedMemorySize, GEMM_SMEM);
    cudaFuncSetAttribute(attn_f16, cudaFuncAttributeMaxDynamicSharedMemorySize, ATTN_SMEM2);

    // one fused conversion pass: x + all 4 weights
    conv_all<<<(8 * NW) / 1024, 256>>>(x, wq, wk, wv, wo, xh, wh);

    // fused QKV projection (N = 6144): q/k fp16 rows, v fp16 transposed
    gemm5<1><<<dim3(3 * D_MODEL / 128, M_TOTAL / 128), 128, GEMM_SMEM>>>(
        xh, wh, qh, kh, vt, nullptr);

    // vectorized RoPE
    rope_v<<<(B_ * T_ * N_HEADS * 8) / 256, 256>>>(qh, kh, rc, rs);

    // fp16 attention (BQ=64, double-buffered cp.async K/V tiles)
    attn_f16<<<dim3(T_ / BQ, N_HEADS, B_), 128, ATTN_SMEM2>>>(qh, kh, vt, xh);

    // output projection: fp32 result
    gemm5<0><<<dim3(D_MODEL / 128, M_TOTAL / 128), 128, GEMM_SMEM>>>(
        xh, wh + 3 * (size_t)NW, nullptr, nullptr, nullptr, out);
}

// round 15
// speedup vs baseline: 1.0460x; 1.0460x over previous
#include <cuda_runtime.h>
#include <cuda_fp16.h>
#include <math.h>
#include <stdint.h>

#define D_MODEL 2048
#define N_HEADS 16
#define D_HEAD  128
#define B_      4
#define T_      2048
#define M_TOTAL (B_*T_)   // 8192
#define NW      (D_MODEL*D_MODEL)   // 4194304 = 2^22

// Scratch: __device__ globals (no allocation allowed in kernel_launch).
__device__ __half g_qh[M_TOTAL*D_MODEL];     // fp16 q (rope'd)
__device__ __half g_kh[M_TOTAL*D_MODEL];     // fp16 k (rope'd)
__device__ __half g_vt[M_TOTAL*D_MODEL];     // fp16 v, transposed [b,h][d][t]
__device__ __half g_xh[M_TOTAL*D_MODEL];     // fp16 activations (x, then attn-out)
__device__ __half g_wh[4*NW];                // fp16 weights [wq|wk|wv|wo]

__device__ __forceinline__ uint32_t packh2(float a, float b) {
    __half2 h = __floats2half2_rn(a, b);
    return *(uint32_t*)&h;
}

// One fused fp32->fp16 conversion: x (regions 0..3 of NW) then wq/wk/wv/wo.
__global__ void conv_all(const float* __restrict__ x,
                         const float* __restrict__ wq, const float* __restrict__ wk,
                         const float* __restrict__ wv, const float* __restrict__ wo,
                         __half* __restrict__ xh, __half* __restrict__ wh) {
    size_t i = ((size_t)blockIdx.x * blockDim.x + threadIdx.x) * 4;
    int which = (int)(i >> 22);
    const float* src;
    __half* dst;
    if (which < 4) {
        src = x + i;
        dst = xh + i;
    } else {
        const float* w = (which == 4) ? wq : (which == 5) ? wk : (which == 6) ? wv : wo;
        src = w + (i & (NW - 1));
        dst = wh + (i - 4 * (size_t)NW);
    }
    float4 v = *(const float4*)src;
    uint2 pk;
    pk.x = packh2(v.x, v.y);
    pk.y = packh2(v.z, v.w);
    *(uint2*)dst = pk;
}

#define CP_ASYNC16(dst, src) \
    asm volatile("cp.async.cg.shared.global [%0], [%1], 16;" :: "r"(dst), "l"(src) : "memory")

__device__ __forceinline__ void mma_f16(float* d, const uint32_t* a, const uint32_t* b) {
    asm volatile(
        "mma.sync.aligned.m16n8k16.row.col.f32.f16.f16.f32 "
        "{%0,%1,%2,%3}, {%4,%5,%6,%7}, {%8,%9}, {%0,%1,%2,%3};"
        : "+f"(d[0]), "+f"(d[1]), "+f"(d[2]), "+f"(d[3])
        : "r"(a[0]), "r"(a[1]), "r"(a[2]), "r"(a[3]), "r"(b[0]), "r"(b[1]));
}

// ---------------------------------------------------------------------------
// GEMM (fp16 HMMA): Y = X @ W^T.  CTA 128x128, 4 warps (64x64), 3-stage.
// EPI=1: QKV — write fp16 q/k rows, v transposed [b,h][d][t].
// EPI=0: write fp32 to Yf.
// ---------------------------------------------------------------------------
#define CHH    64
#define SROWH  72
#define NSTH   3
#define STAGE_HALVES (256 * SROWH)
#define STAGE_B      (STAGE_HALVES * 2)
#define BOFF_B       (128 * SROWH * 2)
#define GEMM_SMEM    (NSTH * STAGE_B)       // 110592
#define NCHH  (D_MODEL / CHH)               // 32

template<int EPI>
__global__ __launch_bounds__(128, 2) void gemm5(const __half* __restrict__ X,
                                                const __half* __restrict__ W,
                                                __half* __restrict__ Yq,
                                                __half* __restrict__ Yk,
                                                __half* __restrict__ Yvt,
                                                float* __restrict__ Yf) {
    extern __shared__ __half smh[];
    const uint32_t smem_base = (uint32_t)__cvta_generic_to_shared(smh);

    const int tid  = threadIdx.x;
    const int wid  = tid >> 5;
    const int lane = tid & 31;
    const int qr   = lane >> 2;
    const int qc   = lane & 3;
    const int warpM = wid & 1;
    const int warpN = wid >> 1;

    const int m0      = blockIdx.y * 128;
    const int n_glob  = blockIdx.x * 128;
    const int which   = n_glob >> 11;
    const int n0      = n_glob & 2047;

    const __half* Arow = X + (size_t)m0 * D_MODEL;
    const __half* Brow = W + (size_t)n_glob * D_MODEL;

    float acc[4][8][4];
    #pragma unroll
    for (int mt = 0; mt < 4; mt++)
        #pragma unroll
        for (int nt = 0; nt < 8; nt++)
            #pragma unroll
            for (int c = 0; c < 4; c++) acc[mt][nt][c] = 0.f;

    auto prefetch = [&](int chunk, int stage) {
        const int k0 = chunk * CHH;
        const uint32_t sbase = smem_base + stage * STAGE_B;
        #pragma unroll
        for (int u = 0; u < 16; u++) {
            int idx = tid + u * 128;
            int isB = idx >> 10;
            int i2  = idx & 1023;
            int row = i2 >> 3;
            int seg = i2 & 7;
            const __half* src = (isB ? Brow : Arow) + (size_t)row * D_MODEL + k0 + seg * 8;
            uint32_t dst = sbase + (isB ? BOFF_B : 0) + row * (SROWH * 2) + seg * 16;
            CP_ASYNC16(dst, src);
        }
    };

    prefetch(0, 0);
    asm volatile("cp.async.commit_group;" ::: "memory");
    prefetch(1, 1);
    asm volatile("cp.async.commit_group;" ::: "memory");

    for (int i = 0; i < NCHH; i++) {
        const int stage = i % NSTH;
        asm volatile("cp.async.wait_group 1;" ::: "memory");
        __syncthreads();

        if (i + 2 < NCHH) prefetch(i + 2, (i + 2) % NSTH);
        asm volatile("cp.async.commit_group;" ::: "memory");

        const __half* Acur = smh + stage * STAGE_HALVES;
        const __half* Bcur = Acur + 128 * SROWH;

        #pragma unroll
        for (int k16 = 0; k16 < CHH; k16 += 16) {
            uint32_t a[4][4], b[8][2];
            #pragma unroll
            for (int mt = 0; mt < 4; mt++) {
                int r = warpM * 64 + mt * 16 + qr;
                a[mt][0] = *(const uint32_t*)&Acur[r * SROWH + k16 + 2 * qc];
                a[mt][1] = *(const uint32_t*)&Acur[(r + 8) * SROWH + k16 + 2 * qc];
                a[mt][2] = *(const uint32_t*)&Acur[r * SROWH + k16 + 8 + 2 * qc];
                a[mt][3] = *(const uint32_t*)&Acur[(r + 8) * SROWH + k16 + 8 + 2 * qc];
            }
            #pragma unroll
            for (int nt = 0; nt < 8; nt++) {
                int n = warpN * 64 + nt * 8 + qr;
                b[nt][0] = *(const uint32_t*)&Bcur[n * SROWH + k16 + 2 * qc];
                b[nt][1] = *(const uint32_t*)&Bcur[n * SROWH + k16 + 8 + 2 * qc];
            }
            #pragma unroll
            for (int mt = 0; mt < 4; mt++)
                #pragma unroll
                for (int nt = 0; nt < 8; nt++)
                    mma_f16(acc[mt][nt], a[mt], b[nt]);
        }
    }

    #pragma unroll
    for (int mt = 0; mt < 4; mt++) {
        #pragma unroll
        for (int nt = 0; nt < 8; nt++) {
            int r0 = m0 + warpM * 64 + mt * 16 + qr;
            int cc = n0 + warpN * 64 + nt * 8 + qc * 2;
            float o0 = acc[mt][nt][0], o1 = acc[mt][nt][1];
            float o2 = acc[mt][nt][2], o3 = acc[mt][nt][3];
            if (EPI == 0) {
                *(float2*)&Yf[(size_t)r0 * D_MODEL + cc]       = make_float2(o0, o1);
                *(float2*)&Yf[(size_t)(r0 + 8) * D_MODEL + cc] = make_float2(o2, o3);
            } else if (which < 2) {
                __half* Yh = (which == 0) ? Yq : Yk;
                *(uint32_t*)&Yh[(size_t)r0 * D_MODEL + cc]       = packh2(o0, o1);
                *(uint32_t*)&Yh[(size_t)(r0 + 8) * D_MODEL + cc] = packh2(o2, o3);
            } else {
                int hh = cc >> 7, d = cc & 127;
                int bb = r0 >> 11, tt = r0 & 2047;
                size_t base = ((size_t)(bb * N_HEADS + hh) * D_HEAD + d) * T_ + tt;
                Yvt[base]          = __float2half_rn(o0);
                Yvt[base + T_]     = __float2half_rn(o1);
                Yvt[base + 8]      = __float2half_rn(o2);
                Yvt[base + T_ + 8] = __float2half_rn(o3);
            }
        }
    }
}

// ---------------------------------------------------------------------------
// Vectorized RoPE in-place on fp16 q,k.
// ---------------------------------------------------------------------------
__global__ void rope_v(__half* __restrict__ q, __half* __restrict__ k,
                       const float* __restrict__ cosb, const float* __restrict__ sinb) {
    int idx = blockIdx.x * blockDim.x + threadIdx.x;   // B*T*H*8
    int seg = idx & 7;
    int h   = (idx >> 3) & (N_HEADS - 1);
    int t   = (idx >> 7) & (T_ - 1);
    int b   = idx >> 18;
    int d0  = seg * 8;
    size_t base = ((size_t)(b * T_ + t) * D_MODEL) + h * D_HEAD;

    float c0[8], s0[8], c1[8], s1[8];
    #pragma unroll
    for (int j = 0; j < 8; j += 4) {
        *(float4*)&c0[j] = *(const float4*)&cosb[t * D_HEAD + d0 + j];
        *(float4*)&s0[j] = *(const float4*)&sinb[t * D_HEAD + d0 + j];
        *(float4*)&c1[j] = *(const float4*)&cosb[t * D_HEAD + d0 + 64 + j];
        *(float4*)&s1[j] = *(const float4*)&sinb[t * D_HEAD + d0 + 64 + j];
    }

    union U8 { uint4 u; __half h[8]; };
    U8 qlo, qhi, klo, khi, oql, oqh, okl, okh;
    qlo.u = *(uint4*)&q[base + d0];
    qhi.u = *(uint4*)&q[base + d0 + 64];
    klo.u = *(uint4*)&k[base + d0];
    khi.u = *(uint4*)&k[base + d0 + 64];

    #pragma unroll
    for (int j = 0; j < 8; j++) {
        float ql = __half2float(qlo.h[j]), qh = __half2float(qhi.h[j]);
        oql.h[j] = __float2half_rn(ql * c0[j] - qh * s0[j]);
        oqh.h[j] = __float2half_rn(qh * c1[j] + ql * s1[j]);
        float kl = __half2float(klo.h[j]), kh = __half2float(khi.h[j]);
        okl.h[j] = __float2half_rn(kl * c0[j] - kh * s0[j]);
        okh.h[j] = __float2half_rn(kh * c1[j] + kl * s1[j]);
    }
    *(uint4*)&q[base + d0]      = oql.u;
    *(uint4*)&q[base + d0 + 64] = oqh.u;
    *(uint4*)&k[base + d0]      = okl.u;
    *(uint4*)&k[base + d0 + 64] = okh.u;
}

// ---------------------------------------------------------------------------
// fp16 flash attention (causal, m16n8k16).  Block (qt,h,b), 4 warps,
// warp owns 16 q-rows.  P stays in registers (C->A fragment identity).
// EXACT R8/R11 configuration — the measured optimum.  Do not perturb:
// diagonal skips (fine or coarse) and cp.async tiles all measurably regress.
// ---------------------------------------------------------------------------
#define BQ    64
#define BK    64
#define KPADH 136    // halves per Ks row (128 + 8)
#define VPADH 72     // halves per Vst row (64 + 8)

__global__ __launch_bounds__(128) void attn_f16(const __half* __restrict__ Q,
                                                const __half* __restrict__ K,
                                                const __half* __restrict__ vT,
                                                __half* __restrict__ O) {
    __shared__ __half Ks [BK * KPADH];      // [key][dim]
    __shared__ __half Vst[D_HEAD * VPADH];  // [dim][key]

    const int qt = blockIdx.x, h = blockIdx.y, b = blockIdx.z;
    const int tid  = threadIdx.x;
    const int w    = tid >> 5;
    const int lane = tid & 31;
    const int qr   = lane >> 2;
    const int qc   = lane & 3;

    const int rowL0 = w * 16 + qr;
    const int rowL1 = rowL0 + 8;
    const size_t qg0 = (size_t)(b * T_ + qt * BQ + rowL0) * D_MODEL + h * D_HEAD;
    const size_t qg1 = qg0 + 8 * (size_t)D_MODEL;

    uint32_t qf[8][4];
    #pragma unroll
    for (int j = 0; j < 8; j++) {
        qf[j][0] = *(const uint32_t*)&Q[qg0 + j * 16 + 2 * qc];
        qf[j][1] = *(const uint32_t*)&Q[qg1 + j * 16 + 2 * qc];
        qf[j][2] = *(const uint32_t*)&Q[qg0 + j * 16 + 8 + 2 * qc];
        qf[j][3] = *(const uint32_t*)&Q[qg1 + j * 16 + 8 + 2 * qc];
    }

    float out[16][4];
    #pragma unroll
    for (int nt = 0; nt < 16; nt++)
        #pragma unroll
        for (int c = 0; c < 4; c++) out[nt][c] = 0.f;

    float m0 = -INFINITY, m1 = -INFINITY, l0 = 0.f, l1 = 0.f;
    const float scale = 0.08838834764831845f;

    const __half* vbase = vT + (size_t)(b * N_HEADS + h) * D_HEAD * T_;

    for (int kt = 0; kt <= qt; kt++) {
        __syncthreads();
        #pragma unroll
        for (int u = 0; u < 8; u++) {
            int it = tid + u * 128;
            int r = it >> 4, seg = it & 15;
            *(uint4*)&Ks[r * KPADH + seg * 8] =
                *(const uint4*)&K[(size_t)(b * T_ + kt * BK + r) * D_MODEL + h * D_HEAD + seg * 8];
        }
        #pragma unroll
        for (int u = 0; u < 8; u++) {
            int it = tid + u * 128;
            int d = it >> 3, seg = it & 7;
            *(uint4*)&Vst[d * VPADH + seg * 8] =
                *(const uint4*)&vbase[(size_t)d * T_ + kt * BK + seg * 8];
        }
        __syncthreads();

        float s[8][4];
        #pragma unroll
        for (int nt = 0; nt < 8; nt++)
            #pragma unroll
            for (int c = 0; c < 4; c++) s[nt][c] = 0.f;

        #pragma unroll
        for (int j = 0; j < 8; j++) {
            #pragma unroll
            for (int nt = 0; nt < 8; nt++) {
                uint32_t bf[2];
                bf[0] = *(const uint32_t*)&Ks[(nt * 8 + qr) * KPADH + j * 16 + 2 * qc];
                bf[1] = *(const uint32_t*)&Ks[(nt * 8 + qr) * KPADH + j * 16 + 8 + 2 * qc];
                mma_f16(s[nt], qf[j], bf);
            }
        }

        const bool diag = (kt == qt);
        #pragma unroll
        for (int nt = 0; nt < 8; nt++) {
            int c0 = nt * 8 + 2 * qc, c1 = c0 + 1;
            if (diag) {
                s[nt][0] = (c0 > rowL0) ? -INFINITY : s[nt][0] * scale;
                s[nt][1] = (c1 > rowL0) ? -INFINITY : s[nt][1] * scale;
                s[nt][2] = (c0 > rowL1) ? -INFINITY : s[nt][2] * scale;
                s[nt][3] = (c1 > rowL1) ? -INFINITY : s[nt][3] * scale;
            } else {
                s[nt][0] *= scale; s[nt][1] *= scale;
                s[nt][2] *= scale; s[nt][3] *= scale;
            }
        }

        float rmax0 = -INFINITY, rmax1 = -INFINITY;
        #pragma unroll
        for (int nt = 0; nt < 8; nt++) {
            rmax0 = fmaxf(rmax0, fmaxf(s[nt][0], s[nt][1]));
            rmax1 = fmaxf(rmax1, fmaxf(s[nt][2], s[nt][3]));
        }
        rmax0 = fmaxf(rmax0, __shfl_xor_sync(0xffffffffu, rmax0, 1));
        rmax0 = fmaxf(rmax0, __shfl_xor_sync(0xffffffffu, rmax0, 2));
        rmax1 = fmaxf(rmax1, __shfl_xor_sync(0xffffffffu, rmax1, 1));
        rmax1 = fmaxf(rmax1, __shfl_xor_sync(0xffffffffu, rmax1, 2));

        float mn0 = fmaxf(m0, rmax0), mn1 = fmaxf(m1, rmax1);
        float a0 = __expf(m0 - mn0),  a1 = __expf(m1 - mn1);

        uint32_t pr0[8], pr1[8];
        float sum0 = 0.f, sum1 = 0.f;
        #pragma unroll
        for (int nt = 0; nt < 8; nt++) {
            float p0 = __expf(s[nt][0] - mn0);
            float p1 = __expf(s[nt][1] - mn0);
            float p2 = __expf(s[nt][2] - mn1);
            float p3 = __expf(s[nt][3] - mn1);
            sum0 += p0 + p1; sum1 += p2 + p3;
            pr0[nt] = packh2(p0, p1);
            pr1[nt] = packh2(p2, p3);
        }
        sum0 += __shfl_xor_sync(0xffffffffu, sum0, 1);
        sum0 += __shfl_xor_sync(0xffffffffu, sum0, 2);
        sum1 += __shfl_xor_sync(0xffffffffu, sum1, 1);
        sum1 += __shfl_xor_sync(0xffffffffu, sum1, 2);

        l0 = l0 * a0 + sum0;
        l1 = l1 * a1 + sum1;
        m0 = mn0; m1 = mn1;

        #pragma unroll
        for (int nt = 0; nt < 16; nt++) {
            out[nt][0] *= a0; out[nt][1] *= a0;
            out[nt][2] *= a1; out[nt][3] *= a1;
        }

        #pragma unroll
        for (int j = 0; j < 4; j++) {
            uint32_t af[4] = { pr0[2 * j], pr1[2 * j], pr0[2 * j + 1], pr1[2 * j + 1] };
            #pragma unroll
            for (int nt = 0; nt < 16; nt++) {
                uint32_t bf[2];
                bf[0] = *(const uint32_t*)&Vst[(nt * 8 + qr) * VPADH + j * 16 + 2 * qc];
                bf[1] = *(const uint32_t*)&Vst[(nt * 8 + qr) * VPADH + j * 16 + 8 + 2 * qc];
                mma_f16(out[nt], af, bf);
            }
        }
    }

    float inv0 = 1.f / l0, inv1 = 1.f / l1;
    #pragma unroll
    for (int nt = 0; nt < 16; nt++) {
        int cc = nt * 8 + 2 * qc;
        *(uint32_t*)&O[qg0 + cc] = packh2(out[nt][0] * inv0, out[nt][1] * inv0);
        *(uint32_t*)&O[qg1 + cc] = packh2(out[nt][2] * inv1, out[nt][3] * inv1);
    }
}

// ---------------------------------------------------------------------------
extern "C" void kernel_launch(void* const* d_in, const int* in_sizes, int n_in,
                              void* d_out, int out_size) {
    const float* x  = (const float*)d_in[0];
    const float* rc = (const float*)d_in[1];
    const float* rs = (const float*)d_in[2];
    const float* wq = (const float*)d_in[3];
    const float* wk = (const float*)d_in[4];
    const float* wv = (const float*)d_in[5];
    const float* wo = (const float*)d_in[6];
    float* out = (float*)d_out;

    __half *qh, *kh, *vt, *xh, *wh;
    cudaGetSymbolAddress((void**)&qh, g_qh);
    cudaGetSymbolAddress((void**)&kh, g_kh);
    cudaGetSymbolAddress((void**)&vt, g_vt);
    cudaGetSymbolAddress((void**)&xh, g_xh);
    cudaGetSymbolAddress((void**)&wh, g_wh);

    cudaFuncSetAttribute(gemm5<1>, cudaFuncAttributeMaxDynamicSharedMemorySize, GEMM_SMEM);
    cudaFuncSetAttribute(gemm5<0>, cudaFuncAttributeMaxDynamicSharedMemorySize, GEMM_SMEM);

    // one fused conversion pass: x + all 4 weights
    conv_all<<<(8 * NW) / 1024, 256>>>(x, wq, wk, wv, wo, xh, wh);

    // fused QKV projection (N = 6144): q/k fp16 rows, v fp16 transposed
    gemm5<1><<<dim3(3 * D_MODEL / 128, M_TOTAL / 128), 128, GEMM_SMEM>>>(
        xh, wh, qh, kh, vt, nullptr);

    // vectorized RoPE
    rope_v<<<(B_ * T_ * N_HEADS * 8) / 256, 256>>>(qh, kh, rc, rs);

    // fp16 attention (BQ=64, natural order — proven optimum)
    attn_f16<<<dim3(T_ / BQ, N_HEADS, B_), 128>>>(qh, kh, vt, xh);

    // output projection: fp32 result
    gemm5<0><<<dim3(D_MODEL / 128, M_TOTAL / 128), 128, GEMM_SMEM>>>(
        xh, wh + 3 * (size_t)NW, nullptr, nullptr, nullptr, out);
}

// round 16
// speedup vs baseline: 1.0526x; 1.0063x over previous
#include <cuda_runtime.h>
#include <cuda_fp16.h>
#include <math.h>
#include <stdint.h>

#define D_MODEL 2048
#define N_HEADS 16
#define D_HEAD  128
#define B_      4
#define T_      2048
#define M_TOTAL (B_*T_)   // 8192
#define NW      (D_MODEL*D_MODEL)   // 4194304 = 2^22

// Scratch: __device__ globals (no allocation allowed in kernel_launch).
__device__ __half g_qh[M_TOTAL*D_MODEL];     // fp16 q (rope'd, pre-scaled)
__device__ __half g_kh[M_TOTAL*D_MODEL];     // fp16 k (rope'd)
__device__ __half g_vt[M_TOTAL*D_MODEL];     // fp16 v, transposed [b,h][d][t]
__device__ __half g_xh[M_TOTAL*D_MODEL];     // fp16 activations (x, then attn-out)
__device__ __half g_wh[4*NW];                // fp16 weights [wq|wk|wv|wo]

__device__ __forceinline__ uint32_t packh2(float a, float b) {
    __half2 h = __floats2half2_rn(a, b);
    return *(uint32_t*)&h;
}

// One fused fp32->fp16 conversion: x (regions 0..3 of NW) then wq/wk/wv/wo.
__global__ void conv_all(const float* __restrict__ x,
                         const float* __restrict__ wq, const float* __restrict__ wk,
                         const float* __restrict__ wv, const float* __restrict__ wo,
                         __half* __restrict__ xh, __half* __restrict__ wh) {
    size_t i = ((size_t)blockIdx.x * blockDim.x + threadIdx.x) * 4;
    int which = (int)(i >> 22);
    const float* src;
    __half* dst;
    if (which < 4) {
        src = x + i;
        dst = xh + i;
    } else {
        const float* w = (which == 4) ? wq : (which == 5) ? wk : (which == 6) ? wv : wo;
        src = w + (i & (NW - 1));
        dst = wh + (i - 4 * (size_t)NW);
    }
    float4 v = *(const float4*)src;
    uint2 pk;
    pk.x = packh2(v.x, v.y);
    pk.y = packh2(v.z, v.w);
    *(uint2*)dst = pk;
}

#define CP_ASYNC16(dst, src) \
    asm volatile("cp.async.cg.shared.global [%0], [%1], 16;" :: "r"(dst), "l"(src) : "memory")

__device__ __forceinline__ void mma_f16(float* d, const uint32_t* a, const uint32_t* b) {
    asm volatile(
        "mma.sync.aligned.m16n8k16.row.col.f32.f16.f16.f32 "
        "{%0,%1,%2,%3}, {%4,%5,%6,%7}, {%8,%9}, {%0,%1,%2,%3};"
        : "+f"(d[0]), "+f"(d[1]), "+f"(d[2]), "+f"(d[3])
        : "r"(a[0]), "r"(a[1]), "r"(a[2]), "r"(a[3]), "r"(b[0]), "r"(b[1]));
}

// ---------------------------------------------------------------------------
// GEMM (fp16 HMMA): Y = X @ W^T.  CTA 128x128, 4 warps (64x64), 3-stage.
// EPI=1: QKV — write fp16 q/k rows, v transposed [b,h][d][t].
// EPI=0: write fp32 to Yf.
// ---------------------------------------------------------------------------
#define CHH    64
#define SROWH  72
#define NSTH   3
#define STAGE_HALVES (256 * SROWH)
#define STAGE_B      (STAGE_HALVES * 2)
#define BOFF_B       (128 * SROWH * 2)
#define GEMM_SMEM    (NSTH * STAGE_B)       // 110592
#define NCHH  (D_MODEL / CHH)               // 32

template<int EPI>
__global__ __launch_bounds__(128, 2) void gemm5(const __half* __restrict__ X,
                                                const __half* __restrict__ W,
                                                __half* __restrict__ Yq,
                                                __half* __restrict__ Yk,
                                                __half* __restrict__ Yvt,
                                                float* __restrict__ Yf) {
    extern __shared__ __half smh[];
    const uint32_t smem_base = (uint32_t)__cvta_generic_to_shared(smh);

    const int tid  = threadIdx.x;
    const int wid  = tid >> 5;
    const int lane = tid & 31;
    const int qr   = lane >> 2;
    const int qc   = lane & 3;
    const int warpM = wid & 1;
    const int warpN = wid >> 1;

    const int m0      = blockIdx.y * 128;
    const int n_glob  = blockIdx.x * 128;
    const int which   = n_glob >> 11;
    const int n0      = n_glob & 2047;

    const __half* Arow = X + (size_t)m0 * D_MODEL;
    const __half* Brow = W + (size_t)n_glob * D_MODEL;

    float acc[4][8][4];
    #pragma unroll
    for (int mt = 0; mt < 4; mt++)
        #pragma unroll
        for (int nt = 0; nt < 8; nt++)
            #pragma unroll
            for (int c = 0; c < 4; c++) acc[mt][nt][c] = 0.f;

    auto prefetch = [&](int chunk, int stage) {
        const int k0 = chunk * CHH;
        const uint32_t sbase = smem_base + stage * STAGE_B;
        #pragma unroll
        for (int u = 0; u < 16; u++) {
            int idx = tid + u * 128;
            int isB = idx >> 10;
            int i2  = idx & 1023;
            int row = i2 >> 3;
            int seg = i2 & 7;
            const __half* src = (isB ? Brow : Arow) + (size_t)row * D_MODEL + k0 + seg * 8;
            uint32_t dst = sbase + (isB ? BOFF_B : 0) + row * (SROWH * 2) + seg * 16;
            CP_ASYNC16(dst, src);
        }
    };

    prefetch(0, 0);
    asm volatile("cp.async.commit_group;" ::: "memory");
    prefetch(1, 1);
    asm volatile("cp.async.commit_group;" ::: "memory");

    for (int i = 0; i < NCHH; i++) {
        const int stage = i % NSTH;
        asm volatile("cp.async.wait_group 1;" ::: "memory");
        __syncthreads();

        if (i + 2 < NCHH) prefetch(i + 2, (i + 2) % NSTH);
        asm volatile("cp.async.commit_group;" ::: "memory");

        const __half* Acur = smh + stage * STAGE_HALVES;
        const __half* Bcur = Acur + 128 * SROWH;

        #pragma unroll
        for (int k16 = 0; k16 < CHH; k16 += 16) {
            uint32_t a[4][4], b[8][2];
            #pragma unroll
            for (int mt = 0; mt < 4; mt++) {
                int r = warpM * 64 + mt * 16 + qr;
                a[mt][0] = *(const uint32_t*)&Acur[r * SROWH + k16 + 2 * qc];
                a[mt][1] = *(const uint32_t*)&Acur[(r + 8) * SROWH + k16 + 2 * qc];
                a[mt][2] = *(const uint32_t*)&Acur[r * SROWH + k16 + 8 + 2 * qc];
                a[mt][3] = *(const uint32_t*)&Acur[(r + 8) * SROWH + k16 + 8 + 2 * qc];
            }
            #pragma unroll
            for (int nt = 0; nt < 8; nt++) {
                int n = warpN * 64 + nt * 8 + qr;
                b[nt][0] = *(const uint32_t*)&Bcur[n * SROWH + k16 + 2 * qc];
                b[nt][1] = *(const uint32_t*)&Bcur[n * SROWH + k16 + 8 + 2 * qc];
            }
            #pragma unroll
            for (int mt = 0; mt < 4; mt++)
                #pragma unroll
                for (int nt = 0; nt < 8; nt++)
                    mma_f16(acc[mt][nt], a[mt], b[nt]);
        }
    }

    #pragma unroll
    for (int mt = 0; mt < 4; mt++) {
        #pragma unroll
        for (int nt = 0; nt < 8; nt++) {
            int r0 = m0 + warpM * 64 + mt * 16 + qr;
            int cc = n0 + warpN * 64 + nt * 8 + qc * 2;
            float o0 = acc[mt][nt][0], o1 = acc[mt][nt][1];
            float o2 = acc[mt][nt][2], o3 = acc[mt][nt][3];
            if (EPI == 0) {
                *(float2*)&Yf[(size_t)r0 * D_MODEL + cc]       = make_float2(o0, o1);
                *(float2*)&Yf[(size_t)(r0 + 8) * D_MODEL + cc] = make_float2(o2, o3);
            } else if (which < 2) {
                __half* Yh = (which == 0) ? Yq : Yk;
                *(uint32_t*)&Yh[(size_t)r0 * D_MODEL + cc]       = packh2(o0, o1);
                *(uint32_t*)&Yh[(size_t)(r0 + 8) * D_MODEL + cc] = packh2(o2, o3);
            } else {
                int hh = cc >> 7, d = cc & 127;
                int bb = r0 >> 11, tt = r0 & 2047;
                size_t base = ((size_t)(bb * N_HEADS + hh) * D_HEAD + d) * T_ + tt;
                Yvt[base]          = __float2half_rn(o0);
                Yvt[base + T_]     = __float2half_rn(o1);
                Yvt[base + 8]      = __float2half_rn(o2);
                Yvt[base + T_ + 8] = __float2half_rn(o3);
            }
        }
    }
}

// ---------------------------------------------------------------------------
// Vectorized RoPE in-place on fp16 q,k.  Q outputs are PRE-SCALED by
// 1/sqrt(D_HEAD) so the attention kernel needs no score scaling.
// ---------------------------------------------------------------------------
__global__ void rope_v(__half* __restrict__ q, __half* __restrict__ k,
                       const float* __restrict__ cosb, const float* __restrict__ sinb) {
    const float qsc = 0.08838834764831845f;   // 1/sqrt(128)
    int idx = blockIdx.x * blockDim.x + threadIdx.x;   // B*T*H*8
    int seg = idx & 7;
    int h   = (idx >> 3) & (N_HEADS - 1);
    int t   = (idx >> 7) & (T_ - 1);
    int b   = idx >> 18;
    int d0  = seg * 8;
    size_t base = ((size_t)(b * T_ + t) * D_MODEL) + h * D_HEAD;

    float c0[8], s0[8], c1[8], s1[8];
    #pragma unroll
    for (int j = 0; j < 8; j += 4) {
        *(float4*)&c0[j] = *(const float4*)&cosb[t * D_HEAD + d0 + j];
        *(float4*)&s0[j] = *(const float4*)&sinb[t * D_HEAD + d0 + j];
        *(float4*)&c1[j] = *(const float4*)&cosb[t * D_HEAD + d0 + 64 + j];
        *(float4*)&s1[j] = *(const float4*)&sinb[t * D_HEAD + d0 + 64 + j];
    }

    union U8 { uint4 u; __half h[8]; };
    U8 qlo, qhi, klo, khi, oql, oqh, okl, okh;
    qlo.u = *(uint4*)&q[base + d0];
    qhi.u = *(uint4*)&q[base + d0 + 64];
    klo.u = *(uint4*)&k[base + d0];
    khi.u = *(uint4*)&k[base + d0 + 64];

    #pragma unroll
    for (int j = 0; j < 8; j++) {
        float ql = __half2float(qlo.h[j]), qh = __half2float(qhi.h[j]);
        oql.h[j] = __float2half_rn((ql * c0[j] - qh * s0[j]) * qsc);
        oqh.h[j] = __float2half_rn((qh * c1[j] + ql * s1[j]) * qsc);
        float kl = __half2float(klo.h[j]), kh = __half2float(khi.h[j]);
        okl.h[j] = __float2half_rn(kl * c0[j] - kh * s0[j]);
        okh.h[j] = __float2half_rn(kh * c1[j] + kl * s1[j]);
    }
    *(uint4*)&q[base + d0]      = oql.u;
    *(uint4*)&q[base + d0 + 64] = oqh.u;
    *(uint4*)&k[base + d0]      = okl.u;
    *(uint4*)&k[base + d0 + 64] = okh.u;
}

// ---------------------------------------------------------------------------
// fp16 flash attention (causal, m16n8k16).  EXACT R11 structure; q arrives
// pre-scaled, so the softmax section has no scale multiplies (pure select on
// the diagonal, no-op elsewhere).  MMA loops untouched.
// ---------------------------------------------------------------------------
#define BQ    64
#define BK    64
#define KPADH 136    // halves per Ks row (128 + 8)
#define VPADH 72     // halves per Vst row (64 + 8)

__global__ __launch_bounds__(128) void attn_f16(const __half* __restrict__ Q,
                                                const __half* __restrict__ K,
                                                const __half* __restrict__ vT,
                                                __half* __restrict__ O) {
    __shared__ __half Ks [BK * KPADH];      // [key][dim]
    __shared__ __half Vst[D_HEAD * VPADH];  // [dim][key]

    const int qt = blockIdx.x, h = blockIdx.y, b = blockIdx.z;
    const int tid  = threadIdx.x;
    const int w    = tid >> 5;
    const int lane = tid & 31;
    const int qr   = lane >> 2;
    const int qc   = lane & 3;

    const int rowL0 = w * 16 + qr;
    const int rowL1 = rowL0 + 8;
    const size_t qg0 = (size_t)(b * T_ + qt * BQ + rowL0) * D_MODEL + h * D_HEAD;
    const size_t qg1 = qg0 + 8 * (size_t)D_MODEL;

    uint32_t qf[8][4];
    #pragma unroll
    for (int j = 0; j < 8; j++) {
        qf[j][0] = *(const uint32_t*)&Q[qg0 + j * 16 + 2 * qc];
        qf[j][1] = *(const uint32_t*)&Q[qg1 + j * 16 + 2 * qc];
        qf[j][2] = *(const uint32_t*)&Q[qg0 + j * 16 + 8 + 2 * qc];
        qf[j][3] = *(const uint32_t*)&Q[qg1 + j * 16 + 8 + 2 * qc];
    }

    float out[16][4];
    #pragma unroll
    for (int nt = 0; nt < 16; nt++)
        #pragma unroll
        for (int c = 0; c < 4; c++) out[nt][c] = 0.f;

    float m0 = -INFINITY, m1 = -INFINITY, l0 = 0.f, l1 = 0.f;

    const __half* vbase = vT + (size_t)(b * N_HEADS + h) * D_HEAD * T_;

    for (int kt = 0; kt <= qt; kt++) {
        __syncthreads();
        #pragma unroll
        for (int u = 0; u < 8; u++) {
            int it = tid + u * 128;
            int r = it >> 4, seg = it & 15;
            *(uint4*)&Ks[r * KPADH + seg * 8] =
                *(const uint4*)&K[(size_t)(b * T_ + kt * BK + r) * D_MODEL + h * D_HEAD + seg * 8];
        }
        #pragma unroll
        for (int u = 0; u < 8; u++) {
            int it = tid + u * 128;
            int d = it >> 3, seg = it & 7;
            *(uint4*)&Vst[d * VPADH + seg * 8] =
                *(const uint4*)&vbase[(size_t)d * T_ + kt * BK + seg * 8];
        }
        __syncthreads();

        float s[8][4];
        #pragma unroll
        for (int nt = 0; nt < 8; nt++)
            #pragma unroll
            for (int c = 0; c < 4; c++) s[nt][c] = 0.f;

        #pragma unroll
        for (int j = 0; j < 8; j++) {
            #pragma unroll
            for (int nt = 0; nt < 8; nt++) {
                uint32_t bf[2];
                bf[0] = *(const uint32_t*)&Ks[(nt * 8 + qr) * KPADH + j * 16 + 2 * qc];
                bf[1] = *(const uint32_t*)&Ks[(nt * 8 + qr) * KPADH + j * 16 + 8 + 2 * qc];
                mma_f16(s[nt], qf[j], bf);
            }
        }

        // causal mask only (q pre-scaled in rope_v)
        if (kt == qt) {
            #pragma unroll
            for (int nt = 0; nt < 8; nt++) {
                int c0 = nt * 8 + 2 * qc, c1 = c0 + 1;
                if (c0 > rowL0) s[nt][0] = -INFINITY;
                if (c1 > rowL0) s[nt][1] = -INFINITY;
                if (c0 > rowL1) s[nt][2] = -INFINITY;
                if (c1 > rowL1) s[nt][3] = -INFINITY;
            }
        }

        float rmax0 = -INFINITY, rmax1 = -INFINITY;
        #pragma unroll
        for (int nt = 0; nt < 8; nt++) {
            rmax0 = fmaxf(rmax0, fmaxf(s[nt][0], s[nt][1]));
            rmax1 = fmaxf(rmax1, fmaxf(s[nt][2], s[nt][3]));
        }
        rmax0 = fmaxf(rmax0, __shfl_xor_sync(0xffffffffu, rmax0, 1));
        rmax0 = fmaxf(rmax0, __shfl_xor_sync(0xffffffffu, rmax0, 2));
        rmax1 = fmaxf(rmax1, __shfl_xor_sync(0xffffffffu, rmax1, 1));
        rmax1 = fmaxf(rmax1, __shfl_xor_sync(0xffffffffu, rmax1, 2));

        float mn0 = fmaxf(m0, rmax0), mn1 = fmaxf(m1, rmax1);
        float a0 = __expf(m0 - mn0),  a1 = __expf(m1 - mn1);

        uint32_t pr0[8], pr1[8];
        float sum0 = 0.f, sum1 = 0.f;
        #pragma unroll
        for (int nt = 0; nt < 8; nt++) {
            float p0 = __expf(s[nt][0] - mn0);
            float p1 = __expf(s[nt][1] - mn0);
            float p2 = __expf(s[nt][2] - mn1);
            float p3 = __expf(s[nt][3] - mn1);
            sum0 += p0 + p1; sum1 += p2 + p3;
            pr0[nt] = packh2(p0, p1);
            pr1[nt] = packh2(p2, p3);
        }
        sum0 += __shfl_xor_sync(0xffffffffu, sum0, 1);
        sum0 += __shfl_xor_sync(0xffffffffu, sum0, 2);
        sum1 += __shfl_xor_sync(0xffffffffu, sum1, 1);
        sum1 += __shfl_xor_sync(0xffffffffu, sum1, 2);

        l0 = l0 * a0 + sum0;
        l1 = l1 * a1 + sum1;
        m0 = mn0; m1 = mn1;

        #pragma unroll
        for (int nt = 0; nt < 16; nt++) {
            out[nt][0] *= a0; out[nt][1] *= a0;
            out[nt][2] *= a1; out[nt][3] *= a1;
        }

        #pragma unroll
        for (int j = 0; j < 4; j++) {
            uint32_t af[4] = { pr0[2 * j], pr1[2 * j], pr0[2 * j + 1], pr1[2 * j + 1] };
            #pragma unroll
            for (int nt = 0; nt < 16; nt++) {
                uint32_t bf[2];
                bf[0] = *(const uint32_t*)&Vst[(nt * 8 + qr) * VPADH + j * 16 + 2 * qc];
                bf[1] = *(const uint32_t*)&Vst[(nt * 8 + qr) * VPADH + j * 16 + 8 + 2 * qc];
                mma_f16(out[nt], af, bf);
            }
        }
    }

    float inv0 = 1.f / l0, inv1 = 1.f / l1;
    #pragma unroll
    for (int nt = 0; nt < 16; nt++) {
        int cc = nt * 8 + 2 * qc;
        *(uint32_t*)&O[qg0 + cc] = packh2(out[nt][0] * inv0, out[nt][1] * inv0);
        *(uint32_t*)&O[qg1 + cc] = packh2(out[nt][2] * inv1, out[nt][3] * inv1);
    }
}

// ---------------------------------------------------------------------------
extern "C" void kernel_launch(void* const* d_in, const int* in_sizes, int n_in,
                              void* d_out, int out_size) {
    const float* x  = (const float*)d_in[0];
    const float* rc = (const float*)d_in[1];
    const float* rs = (const float*)d_in[2];
    const float* wq = (const float*)d_in[3];
    const float* wk = (const float*)d_in[4];
    const float* wv = (const float*)d_in[5];
    const float* wo = (const float*)d_in[6];
    float* out = (float*)d_out;

    __half *qh, *kh, *vt, *xh, *wh;
    cudaGetSymbolAddress((void**)&qh, g_qh);
    cudaGetSymbolAddress((void**)&kh, g_kh);
    cudaGetSymbolAddress((void**)&vt, g_vt);
    cudaGetSymbolAddress((void**)&xh, g_xh);
    cudaGetSymbolAddress((void**)&wh, g_wh);

    cudaFuncSetAttribute(gemm5<1>, cudaFuncAttributeMaxDynamicSharedMemorySize, GEMM_SMEM);
    cudaFuncSetAttribute(gemm5<0>, cudaFuncAttributeMaxDynamicSharedMemorySize, GEMM_SMEM);

    // one fused conversion pass: x + all 4 weights
    conv_all<<<(8 * NW) / 1024, 256>>>(x, wq, wk, wv, wo, xh, wh);

    // fused QKV projection (N = 6144): q/k fp16 rows, v fp16 transposed
    gemm5<1><<<dim3(3 * D_MODEL / 128, M_TOTAL / 128), 128, GEMM_SMEM>>>(
        xh, wh, qh, kh, vt, nullptr);

    // vectorized RoPE (q pre-scaled by 1/sqrt(D_HEAD))
    rope_v<<<(B_ * T_ * N_HEADS * 8) / 256, 256>>>(qh, kh, rc, rs);

    // fp16 attention (BQ=64, natural order)
    attn_f16<<<dim3(T_ / BQ, N_HEADS, B_), 128>>>(qh, kh, vt, xh);

    // output projection: fp32 result
    gemm5<0><<<dim3(D_MODEL / 128, M_TOTAL / 128), 128, GEMM_SMEM>>>(
        xh, wh + 3 * (size_t)NW, nullptr, nullptr, nullptr, out);
}

// round 17
// speedup vs baseline: 1.0547x; 1.0020x over previous
#include <cuda_runtime.h>
#include <cuda_fp16.h>
#include <math.h>
#include <stdint.h>

#define D_MODEL 2048
#define N_HEADS 16
#define D_HEAD  128
#define B_      4
#define T_      2048
#define M_TOTAL (B_*T_)   // 8192
#define NW      (D_MODEL*D_MODEL)   // 4194304 = 2^22

// Scratch: __device__ globals (no allocation allowed in kernel_launch).
__device__ __half g_qh[M_TOTAL*D_MODEL];     // fp16 q (rope'd, pre-scaled by qsc*log2e)
__device__ __half g_kh[M_TOTAL*D_MODEL];     // fp16 k (rope'd)
__device__ __half g_vt[M_TOTAL*D_MODEL];     // fp16 v, transposed [b,h][d][t]
__device__ __half g_xh[M_TOTAL*D_MODEL];     // fp16 activations (x, then attn-out)
__device__ __half g_wh[4*NW];                // fp16 weights [wq|wk|wv|wo]

__device__ __forceinline__ uint32_t packh2(float a, float b) {
    __half2 h = __floats2half2_rn(a, b);
    return *(uint32_t*)&h;
}

__device__ __forceinline__ float ex2f(float x) {   // raw MUFU.EX2 (base-2 exp)
    float r;
    asm("ex2.approx.f32 %0, %1;" : "=f"(r) : "f"(x));
    return r;
}

// One fused fp32->fp16 conversion: x (regions 0..3 of NW) then wq/wk/wv/wo.
__global__ void conv_all(const float* __restrict__ x,
                         const float* __restrict__ wq, const float* __restrict__ wk,
                         const float* __restrict__ wv, const float* __restrict__ wo,
                         __half* __restrict__ xh, __half* __restrict__ wh) {
    size_t i = ((size_t)blockIdx.x * blockDim.x + threadIdx.x) * 4;
    int which = (int)(i >> 22);
    const float* src;
    __half* dst;
    if (which < 4) {
        src = x + i;
        dst = xh + i;
    } else {
        const float* w = (which == 4) ? wq : (which == 5) ? wk : (which == 6) ? wv : wo;
        src = w + (i & (NW - 1));
        dst = wh + (i - 4 * (size_t)NW);
    }
    float4 v = *(const float4*)src;
    uint2 pk;
    pk.x = packh2(v.x, v.y);
    pk.y = packh2(v.z, v.w);
    *(uint2*)dst = pk;
}

#define CP_ASYNC16(dst, src) \
    asm volatile("cp.async.cg.shared.global [%0], [%1], 16;" :: "r"(dst), "l"(src) : "memory")

__device__ __forceinline__ void mma_f16(float* d, const uint32_t* a, const uint32_t* b) {
    asm volatile(
        "mma.sync.aligned.m16n8k16.row.col.f32.f16.f16.f32 "
        "{%0,%1,%2,%3}, {%4,%5,%6,%7}, {%8,%9}, {%0,%1,%2,%3};"
        : "+f"(d[0]), "+f"(d[1]), "+f"(d[2]), "+f"(d[3])
        : "r"(a[0]), "r"(a[1]), "r"(a[2]), "r"(a[3]), "r"(b[0]), "r"(b[1]));
}

// ---------------------------------------------------------------------------
// GEMM (fp16 HMMA): Y = X @ W^T.  CTA 128x128, 4 warps (64x64), 3-stage.
// EPI=1: QKV — write fp16 q/k rows, v transposed [b,h][d][t].
// EPI=0: write fp32 to Yf.
// ---------------------------------------------------------------------------
#define CHH    64
#define SROWH  72
#define NSTH   3
#define STAGE_HALVES (256 * SROWH)
#define STAGE_B      (STAGE_HALVES * 2)
#define BOFF_B       (128 * SROWH * 2)
#define GEMM_SMEM    (NSTH * STAGE_B)       // 110592
#define NCHH  (D_MODEL / CHH)               // 32

template<int EPI>
__global__ __launch_bounds__(128, 2) void gemm5(const __half* __restrict__ X,
                                                const __half* __restrict__ W,
                                                __half* __restrict__ Yq,
                                                __half* __restrict__ Yk,
                                                __half* __restrict__ Yvt,
                                                float* __restrict__ Yf) {
    extern __shared__ __half smh[];
    const uint32_t smem_base = (uint32_t)__cvta_generic_to_shared(smh);

    const int tid  = threadIdx.x;
    const int wid  = tid >> 5;
    const int lane = tid & 31;
    const int qr   = lane >> 2;
    const int qc   = lane & 3;
    const int warpM = wid & 1;
    const int warpN = wid >> 1;

    const int m0      = blockIdx.y * 128;
    const int n_glob  = blockIdx.x * 128;
    const int which   = n_glob >> 11;
    const int n0      = n_glob & 2047;

    const __half* Arow = X + (size_t)m0 * D_MODEL;
    const __half* Brow = W + (size_t)n_glob * D_MODEL;

    float acc[4][8][4];
    #pragma unroll
    for (int mt = 0; mt < 4; mt++)
        #pragma unroll
        for (int nt = 0; nt < 8; nt++)
            #pragma unroll
            for (int c = 0; c < 4; c++) acc[mt][nt][c] = 0.f;

    auto prefetch = [&](int chunk, int stage) {
        const int k0 = chunk * CHH;
        const uint32_t sbase = smem_base + stage * STAGE_B;
        #pragma unroll
        for (int u = 0; u < 16; u++) {
            int idx = tid + u * 128;
            int isB = idx >> 10;
            int i2  = idx & 1023;
            int row = i2 >> 3;
            int seg = i2 & 7;
            const __half* src = (isB ? Brow : Arow) + (size_t)row * D_MODEL + k0 + seg * 8;
            uint32_t dst = sbase + (isB ? BOFF_B : 0) + row * (SROWH * 2) + seg * 16;
            CP_ASYNC16(dst, src);
        }
    };

    prefetch(0, 0);
    asm volatile("cp.async.commit_group;" ::: "memory");
    prefetch(1, 1);
    asm volatile("cp.async.commit_group;" ::: "memory");

    for (int i = 0; i < NCHH; i++) {
        const int stage = i % NSTH;
        asm volatile("cp.async.wait_group 1;" ::: "memory");
        __syncthreads();

        if (i + 2 < NCHH) prefetch(i + 2, (i + 2) % NSTH);
        asm volatile("cp.async.commit_group;" ::: "memory");

        const __half* Acur = smh + stage * STAGE_HALVES;
        const __half* Bcur = Acur + 128 * SROWH;

        #pragma unroll
        for (int k16 = 0; k16 < CHH; k16 += 16) {
            uint32_t a[4][4], b[8][2];
            #pragma unroll
            for (int mt = 0; mt < 4; mt++) {
                int r = warpM * 64 + mt * 16 + qr;
                a[mt][0] = *(const uint32_t*)&Acur[r * SROWH + k16 + 2 * qc];
                a[mt][1] = *(const uint32_t*)&Acur[(r + 8) * SROWH + k16 + 2 * qc];
                a[mt][2] = *(const uint32_t*)&Acur[r * SROWH + k16 + 8 + 2 * qc];
                a[mt][3] = *(const uint32_t*)&Acur[(r + 8) * SROWH + k16 + 8 + 2 * qc];
            }
            #pragma unroll
            for (int nt = 0; nt < 8; nt++) {
                int n = warpN * 64 + nt * 8 + qr;
                b[nt][0] = *(const uint32_t*)&Bcur[n * SROWH + k16 + 2 * qc];
                b[nt][1] = *(const uint32_t*)&Bcur[n * SROWH + k16 + 8 + 2 * qc];
            }
            #pragma unroll
            for (int mt = 0; mt < 4; mt++)
                #pragma unroll
                for (int nt = 0; nt < 8; nt++)
                    mma_f16(acc[mt][nt], a[mt], b[nt]);
        }
    }

    #pragma unroll
    for (int mt = 0; mt < 4; mt++) {
        #pragma unroll
        for (int nt = 0; nt < 8; nt++) {
            int r0 = m0 + warpM * 64 + mt * 16 + qr;
            int cc = n0 + warpN * 64 + nt * 8 + qc * 2;
            float o0 = acc[mt][nt][0], o1 = acc[mt][nt][1];
            float o2 = acc[mt][nt][2], o3 = acc[mt][nt][3];
            if (EPI == 0) {
                *(float2*)&Yf[(size_t)r0 * D_MODEL + cc]       = make_float2(o0, o1);
                *(float2*)&Yf[(size_t)(r0 + 8) * D_MODEL + cc] = make_float2(o2, o3);
            } else if (which < 2) {
                __half* Yh = (which == 0) ? Yq : Yk;
                *(uint32_t*)&Yh[(size_t)r0 * D_MODEL + cc]       = packh2(o0, o1);
                *(uint32_t*)&Yh[(size_t)(r0 + 8) * D_MODEL + cc] = packh2(o2, o3);
            } else {
                int hh = cc >> 7, d = cc & 127;
                int bb = r0 >> 11, tt = r0 & 2047;
                size_t base = ((size_t)(bb * N_HEADS + hh) * D_HEAD + d) * T_ + tt;
                Yvt[base]          = __float2half_rn(o0);
                Yvt[base + T_]     = __float2half_rn(o1);
                Yvt[base + 8]      = __float2half_rn(o2);
                Yvt[base + T_ + 8] = __float2half_rn(o3);
            }
        }
    }
}

// ---------------------------------------------------------------------------
// Vectorized RoPE in-place on fp16 q,k.  Q outputs PRE-SCALED by
// log2(e)/sqrt(D_HEAD): scores arrive in the log-2 domain so the attention
// softmax uses raw ex2 (no per-element multiplies at all).
// ---------------------------------------------------------------------------
__global__ void rope_v(__half* __restrict__ q, __half* __restrict__ k,
                       const float* __restrict__ cosb, const float* __restrict__ sinb) {
    const float qsc = 0.08838834764831845f * 1.4426950408889634f;  // 1/sqrt(128)*log2(e)
    int idx = blockIdx.x * blockDim.x + threadIdx.x;   // B*T*H*8
    int seg = idx & 7;
    int h   = (idx >> 3) & (N_HEADS - 1);
    int t   = (idx >> 7) & (T_ - 1);
    int b   = idx >> 18;
    int d0  = seg * 8;
    size_t base = ((size_t)(b * T_ + t) * D_MODEL) + h * D_HEAD;

    float c0[8], s0[8], c1[8], s1[8];
    #pragma unroll
    for (int j = 0; j < 8; j += 4) {
        *(float4*)&c0[j] = *(const float4*)&cosb[t * D_HEAD + d0 + j];
        *(float4*)&s0[j] = *(const float4*)&sinb[t * D_HEAD + d0 + j];
        *(float4*)&c1[j] = *(const float4*)&cosb[t * D_HEAD + d0 + 64 + j];
        *(float4*)&s1[j] = *(const float4*)&sinb[t * D_HEAD + d0 + 64 + j];
    }

    union U8 { uint4 u; __half h[8]; };
    U8 qlo, qhi, klo, khi, oql, oqh, okl, okh;
    qlo.u = *(uint4*)&q[base + d0];
    qhi.u = *(uint4*)&q[base + d0 + 64];
    klo.u = *(uint4*)&k[base + d0];
    khi.u = *(uint4*)&k[base + d0 + 64];

    #pragma unroll
    for (int j = 0; j < 8; j++) {
        float ql = __half2float(qlo.h[j]), qh = __half2float(qhi.h[j]);
        oql.h[j] = __float2half_rn((ql * c0[j] - qh * s0[j]) * qsc);
        oqh.h[j] = __float2half_rn((qh * c1[j] + ql * s1[j]) * qsc);
        float kl = __half2float(klo.h[j]), kh = __half2float(khi.h[j]);
        okl.h[j] = __float2half_rn(kl * c0[j] - kh * s0[j]);
        okh.h[j] = __float2half_rn(kh * c1[j] + kl * s1[j]);
    }
    *(uint4*)&q[base + d0]      = oql.u;
    *(uint4*)&q[base + d0 + 64] = oqh.u;
    *(uint4*)&k[base + d0]      = okl.u;
    *(uint4*)&k[base + d0 + 64] = okh.u;
}

// ---------------------------------------------------------------------------
// fp16 flash attention (causal, m16n8k16).  EXACT R11 structure; scores are
// in the log-2 domain (q pre-scaled), softmax uses raw ex2.approx — zero
// scalar multiplies outside the rescale.  MMA loops untouched.
// ---------------------------------------------------------------------------
#define BQ    64
#define BK    64
#define KPADH 136    // halves per Ks row (128 + 8)
#define VPADH 72     // halves per Vst row (64 + 8)

__global__ __launch_bounds__(128) void attn_f16(const __half* __restrict__ Q,
                                                const __half* __restrict__ K,
                                                const __half* __restrict__ vT,
                                                __half* __restrict__ O) {
    __shared__ __half Ks [BK * KPADH];      // [key][dim]
    __shared__ __half Vst[D_HEAD * VPADH];  // [dim][key]

    const int qt = blockIdx.x, h = blockIdx.y, b = blockIdx.z;
    const int tid  = threadIdx.x;
    const int w    = tid >> 5;
    const int lane = tid & 31;
    const int qr   = lane >> 2;
    const int qc   = lane & 3;

    const int rowL0 = w * 16 + qr;
    const int rowL1 = rowL0 + 8;
    const size_t qg0 = (size_t)(b * T_ + qt * BQ + rowL0) * D_MODEL + h * D_HEAD;
    const size_t qg1 = qg0 + 8 * (size_t)D_MODEL;

    uint32_t qf[8][4];
    #pragma unroll
    for (int j = 0; j < 8; j++) {
        qf[j][0] = *(const uint32_t*)&Q[qg0 + j * 16 + 2 * qc];
        qf[j][1] = *(const uint32_t*)&Q[qg1 + j * 16 + 2 * qc];
        qf[j][2] = *(const uint32_t*)&Q[qg0 + j * 16 + 8 + 2 * qc];
        qf[j][3] = *(const uint32_t*)&Q[qg1 + j * 16 + 8 + 2 * qc];
    }

    float out[16][4];
    #pragma unroll
    for (int nt = 0; nt < 16; nt++)
        #pragma unroll
        for (int c = 0; c < 4; c++) out[nt][c] = 0.f;

    float m0 = -INFINITY, m1 = -INFINITY, l0 = 0.f, l1 = 0.f;

    const __half* vbase = vT + (size_t)(b * N_HEADS + h) * D_HEAD * T_;

    for (int kt = 0; kt <= qt; kt++) {
        __syncthreads();
        #pragma unroll
        for (int u = 0; u < 8; u++) {
            int it = tid + u * 128;
            int r = it >> 4, seg = it & 15;
            *(uint4*)&Ks[r * KPADH + seg * 8] =
                *(const uint4*)&K[(size_t)(b * T_ + kt * BK + r) * D_MODEL + h * D_HEAD + seg * 8];
        }
        #pragma unroll
        for (int u = 0; u < 8; u++) {
            int it = tid + u * 128;
            int d = it >> 3, seg = it & 7;
            *(uint4*)&Vst[d * VPADH + seg * 8] =
                *(const uint4*)&vbase[(size_t)d * T_ + kt * BK + seg * 8];
        }
        __syncthreads();

        float s[8][4];
        #pragma unroll
        for (int nt = 0; nt < 8; nt++)
            #pragma unroll
            for (int c = 0; c < 4; c++) s[nt][c] = 0.f;

        #pragma unroll
        for (int j = 0; j < 8; j++) {
            #pragma unroll
            for (int nt = 0; nt < 8; nt++) {
                uint32_t bf[2];
                bf[0] = *(const uint32_t*)&Ks[(nt * 8 + qr) * KPADH + j * 16 + 2 * qc];
                bf[1] = *(const uint32_t*)&Ks[(nt * 8 + qr) * KPADH + j * 16 + 8 + 2 * qc];
                mma_f16(s[nt], qf[j], bf);
            }
        }

        // causal mask only (q pre-scaled in rope_v)
        if (kt == qt) {
            #pragma unroll
            for (int nt = 0; nt < 8; nt++) {
                int c0 = nt * 8 + 2 * qc, c1 = c0 + 1;
                if (c0 > rowL0) s[nt][0] = -INFINITY;
                if (c1 > rowL0) s[nt][1] = -INFINITY;
                if (c0 > rowL1) s[nt][2] = -INFINITY;
                if (c1 > rowL1) s[nt][3] = -INFINITY;
            }
        }

        float rmax0 = -INFINITY, rmax1 = -INFINITY;
        #pragma unroll
        for (int nt = 0; nt < 8; nt++) {
            rmax0 = fmaxf(rmax0, fmaxf(s[nt][0], s[nt][1]));
            rmax1 = fmaxf(rmax1, fmaxf(s[nt][2], s[nt][3]));
        }
        rmax0 = fmaxf(rmax0, __shfl_xor_sync(0xffffffffu, rmax0, 1));
        rmax0 = fmaxf(rmax0, __shfl_xor_sync(0xffffffffu, rmax0, 2));
        rmax1 = fmaxf(rmax1, __shfl_xor_sync(0xffffffffu, rmax1, 1));
        rmax1 = fmaxf(rmax1, __shfl_xor_sync(0xffffffffu, rmax1, 2));

        float mn0 = fmaxf(m0, rmax0), mn1 = fmaxf(m1, rmax1);
        float a0 = ex2f(m0 - mn0),  a1 = ex2f(m1 - mn1);

        uint32_t pr0[8], pr1[8];
        float sum0 = 0.f, sum1 = 0.f;
        #pragma unroll
        for (int nt = 0; nt < 8; nt++) {
            float p0 = ex2f(s[nt][0] - mn0);
            float p1 = ex2f(s[nt][1] - mn0);
            float p2 = ex2f(s[nt][2] - mn1);
            float p3 = ex2f(s[nt][3] - mn1);
            sum0 += p0 + p1; sum1 += p2 + p3;
            pr0[nt] = packh2(p0, p1);
            pr1[nt] = packh2(p2, p3);
        }
        sum0 += __shfl_xor_sync(0xffffffffu, sum0, 1);
        sum0 += __shfl_xor_sync(0xffffffffu, sum0, 2);
        sum1 += __shfl_xor_sync(0xffffffffu, sum1, 1);
        sum1 += __shfl_xor_sync(0xffffffffu, sum1, 2);

        l0 = l0 * a0 + sum0;
        l1 = l1 * a1 + sum1;
        m0 = mn0; m1 = mn1;

        #pragma unroll
        for (int nt = 0; nt < 16; nt++) {
            out[nt][0] *= a0; out[nt][1] *= a0;
            out[nt][2] *= a1; out[nt][3] *= a1;
        }

        #pragma unroll
        for (int j = 0; j < 4; j++) {
            uint32_t af[4] = { pr0[2 * j], pr1[2 * j], pr0[2 * j + 1], pr1[2 * j + 1] };
            #pragma unroll
            for (int nt = 0; nt < 16; nt++) {
                uint32_t bf[2];
                bf[0] = *(const uint32_t*)&Vst[(nt * 8 + qr) * VPADH + j * 16 + 2 * qc];
                bf[1] = *(const uint32_t*)&Vst[(nt * 8 + qr) * VPADH + j * 16 + 8 + 2 * qc];
                mma_f16(out[nt], af, bf);
            }
        }
    }

    float inv0 = 1.f / l0, inv1 = 1.f / l1;
    #pragma unroll
    for (int nt = 0; nt < 16; nt++) {
        int cc = nt * 8 + 2 * qc;
        *(uint32_t*)&O[qg0 + cc] = packh2(out[nt][0] * inv0, out[nt][1] * inv0);
        *(uint32_t*)&O[qg1 + cc] = packh2(out[nt][2] * inv1, out[nt][3] * inv1);
    }
}

// ---------------------------------------------------------------------------
extern "C" void kernel_launch(void* const* d_in, const int* in_sizes, int n_in,
                              void* d_out, int out_size) {
    const float* x  = (const float*)d_in[0];
    const float* rc = (const float*)d_in[1];
    const float* rs = (const float*)d_in[2];
    const float* wq = (const float*)d_in[3];
    const float* wk = (const float*)d_in[4];
    const float* wv = (const float*)d_in[5];
    const float* wo = (const float*)d_in[6];
    float* out = (float*)d_out;

    __half *qh, *kh, *vt, *xh, *wh;
    cudaGetSymbolAddress((void**)&qh, g_qh);
    cudaGetSymbolAddress((void**)&kh, g_kh);
    cudaGetSymbolAddress((void**)&vt, g_vt);
    cudaGetSymbolAddress((void**)&xh, g_xh);
    cudaGetSymbolAddress((void**)&wh, g_wh);

    cudaFuncSetAttribute(gemm5<1>, cudaFuncAttributeMaxDynamicSharedMemorySize, GEMM_SMEM);
    cudaFuncSetAttribute(gemm5<0>, cudaFuncAttributeMaxDynamicSharedMemorySize, GEMM_SMEM);

    // one fused conversion pass: x + all 4 weights
    conv_all<<<(8 * NW) / 1024, 256>>>(x, wq, wk, wv, wo, xh, wh);

    // fused QKV projection (N = 6144): q/k fp16 rows, v fp16 transposed
    gemm5<1><<<dim3(3 * D_MODEL / 128, M_TOTAL / 128), 128, GEMM_SMEM>>>(
        xh, wh, qh, kh, vt, nullptr);

    // vectorized RoPE (q pre-scaled by log2(e)/sqrt(D_HEAD))
    rope_v<<<(B_ * T_ * N_HEADS * 8) / 256, 256>>>(qh, kh, rc, rs);

    // fp16 attention (BQ=64, base-2 softmax)
    attn_f16<<<dim3(T_ / BQ, N_HEADS, B_), 128>>>(qh, kh, vt, xh);

    // output projection: fp32 result
    gemm5<0><<<dim3(D_MODEL / 128, M_TOTAL / 128), 128, GEMM_SMEM>>>(
        xh, wh + 3 * (size_t)NW, nullptr, nullptr, nullptr, out);
}